// round 17
// baseline (speedup 1.0000x reference)
#include <cuda_runtime.h>
#include <cuda_bf16.h>
#include <cuda_fp16.h>
#include <cstdint>

#define D 128
#define NMAX 50000
#define EMAX 800000

// ---------------- scratch (static device globals; no allocation) ----------------
__device__ uint32_t g_H [(size_t)NMAX * 64]; // GEMM output per layer, fp16x2 packed
__device__ float    g_A [(size_t)NMAX * D];  // layer activations (ping), fp32
__device__ float    g_B [(size_t)NMAX * D];  // layer activations (pong), fp32
__device__ uint32_t g_Wh[3 * 64 * 128];      // W hi, packed bf16 k-pairs [p][n]
__device__ uint32_t g_Wl[3 * 64 * 128];      // W lo, packed bf16 k-pairs
__device__ float    g_dinv[NMAX];
__device__ int      g_cnt[NMAX];             // invariant: zero at entry
__device__ int      g_rowstart[NMAX + 1];
__device__ int      g_cursor[NMAX];
__device__ int2     g_cw[EMAX];              // packed (src, weight-bits)
__device__ unsigned long long g_desc[64];    // lookback descriptors (zero at entry)

// ---------------- capture-safe static stream/events (host resources only) ------
static cudaStream_t s2;
static cudaEvent_t  evFork, evJoin, evR1, eB1, eG2, eB2, eG3, eB3;
namespace { struct _Init {
    _Init() {
        cudaStreamCreateWithFlags(&s2, cudaStreamNonBlocking);
        cudaEventCreateWithFlags(&evFork, cudaEventDisableTiming);
        cudaEventCreateWithFlags(&evJoin, cudaEventDisableTiming);
        cudaEventCreateWithFlags(&evR1, cudaEventDisableTiming);
        cudaEventCreateWithFlags(&eB1, cudaEventDisableTiming);
        cudaEventCreateWithFlags(&eG2, cudaEventDisableTiming);
        cudaEventCreateWithFlags(&eB2, cudaEventDisableTiming);
        cudaEventCreateWithFlags(&eG3, cudaEventDisableTiming);
        cudaEventCreateWithFlags(&eB3, cudaEventDisableTiming);
    }
} _init; }

// ---------------- bf16 / mma / async helpers ----------------
__device__ __forceinline__ void bf16_split2(float2 v, uint32_t& hp, uint32_t& lp) {
    __nv_bfloat162 h2 = __float22bfloat162_rn(v);          // low=v.x, high=v.y
    float2 r = make_float2(v.x - __low2float(h2), v.y - __high2float(h2));
    __nv_bfloat162 l2 = __float22bfloat162_rn(r);
    hp = *reinterpret_cast<uint32_t*>(&h2);
    lp = *reinterpret_cast<uint32_t*>(&l2);
}

__device__ __forceinline__ void mma_bf16(float* c, const uint32_t* a,
                                         uint32_t b0, uint32_t b1) {
    asm volatile(
        "mma.sync.aligned.m16n8k16.row.col.f32.bf16.bf16.f32 "
        "{%0,%1,%2,%3}, {%4,%5,%6,%7}, {%8,%9}, {%0,%1,%2,%3};"
        : "+f"(c[0]), "+f"(c[1]), "+f"(c[2]), "+f"(c[3])
        : "r"(a[0]), "r"(a[1]), "r"(a[2]), "r"(a[3]), "r"(b0), "r"(b1));
}

__device__ __forceinline__ void cp_async16(uint32_t saddr, const void* gptr) {
    asm volatile("cp.async.cg.shared.global [%0], [%1], 16;"
                 :: "r"(saddr), "l"(gptr));
}

// unpack 4 halves (uint2) -> float4
__device__ __forceinline__ float4 h4_to_f4(uint2 p) {
    __half2 a = *reinterpret_cast<__half2*>(&p.x);
    __half2 b = *reinterpret_cast<__half2*>(&p.y);
    float2 fa = __half22float2(a);
    float2 fb = __half22float2(b);
    return make_float4(fa.x, fa.y, fb.x, fb.y);
}

// ---------------- W pre-split: pack bf16 k-pairs, all 3 layers ----------------
__global__ void k_wsplit(const float* __restrict__ W1,
                         const float* __restrict__ W2,
                         const float* __restrict__ W3) {
    int layer = blockIdx.y;
    const float* W = (layer == 0) ? W1 : (layer == 1) ? W2 : W3;
    int i = blockIdx.x * 256 + threadIdx.x;      // 0..8191 (grid.x = 32)
    int p = i >> 7, n = i & 127;
    float x0 = W[(2 * p) * D + n];
    float x1 = W[(2 * p + 1) * D + n];
    uint32_t hp, lp;
    bf16_split2(make_float2(x0, x1), hp, lp);
    g_Wh[layer * 8192 + i] = hp;
    g_Wl[layer * 8192 + i] = lp;
}

// ---------------- CSR construction ----------------
__global__ void k_count(const int* __restrict__ dst, int E) {
    int base = (blockIdx.x * blockDim.x + threadIdx.x) * 4;
    if (base >= E) return;
    if (base + 3 < E) {
        int4 d = *(const int4*)(dst + base);
        atomicAdd(&g_cnt[d.x], 1);
        atomicAdd(&g_cnt[d.y], 1);
        atomicAdd(&g_cnt[d.z], 1);
        atomicAdd(&g_cnt[d.w], 1);
    } else {
        for (int j = base; j < E; j++) atomicAdd(&g_cnt[dst[j]], 1);
    }
}

// single-pass exclusive scan via decoupled lookback; self-cleans g_cnt.
__global__ void k_scan_lb(int n) {
    __shared__ int wsum[32];
    __shared__ int s_prefix;
    int tid = threadIdx.x, lane = tid & 31, wid = tid >> 5;
    int b = blockIdx.x;
    int i = b * 1024 + tid;
    int v = (i < n) ? g_cnt[i] : 0;
    if (i < n) g_cnt[i] = 0;               // self-clean for next replay
    int x = v;
    #pragma unroll
    for (int o = 1; o < 32; o <<= 1) {
        int t = __shfl_up_sync(0xffffffffu, x, o);
        if (lane >= o) x += t;
    }
    if (lane == 31) wsum[wid] = x;
    __syncthreads();
    if (wid == 0) {
        int w = wsum[lane];
        #pragma unroll
        for (int o = 1; o < 32; o <<= 1) {
            int t = __shfl_up_sync(0xffffffffu, w, o);
            if (lane >= o) w += t;
        }
        wsum[lane] = w;
    }
    __syncthreads();
    int blockAgg = wsum[31];

    if (tid == 0) {
        if (b == 0) {
            s_prefix = 0;
            atomicExch(&g_desc[0], (2ULL << 32) | (unsigned)blockAgg);
        } else {
            atomicExch(&g_desc[b], (1ULL << 32) | (unsigned)blockAgg);
        }
    }
    if (b > 0 && wid == 0) {
        int prefix = 0;
        int look = b - 1;
        while (true) {
            int idx = look - lane;
            unsigned f; int val;
            if (idx >= 0) {
                unsigned long long d = atomicAdd(&g_desc[idx], 0ULL);
                f = (unsigned)(d >> 32);
                val = (int)(unsigned)d;
            } else { f = 1u; val = 0; }
            if (__ballot_sync(0xffffffffu, f == 0u)) continue;   // retry window
            unsigned bp = __ballot_sync(0xffffffffu, idx >= 0 && f == 2u);
            int stop = bp ? (__ffs(bp) - 1) : 32;
            int xs = (lane <= stop) ? val : 0;
            #pragma unroll
            for (int o = 16; o > 0; o >>= 1)
                xs += __shfl_xor_sync(0xffffffffu, xs, o);
            prefix += xs;
            if (stop < 32) break;
            look -= 32;
        }
        if (lane == 0) {
            s_prefix = prefix;
            atomicExch(&g_desc[b], (2ULL << 32) | (unsigned)(prefix + blockAgg));
        }
    }
    __syncthreads();

    int excl = s_prefix + (wid ? wsum[wid - 1] : 0) + x - v;
    if (i < n) {
        g_rowstart[i] = excl;
        g_cursor[i]   = excl;
        g_dinv[i]     = rsqrtf((float)(v + 1));   // deg incl. self-loop
        if (i == n - 1) g_rowstart[n] = excl + v;
    }
}

__global__ void k_fill(const int* __restrict__ ei, int E) {
    if (blockIdx.x == 0 && threadIdx.x < 64) g_desc[threadIdx.x] = 0ULL;
    int base = (blockIdx.x * blockDim.x + threadIdx.x) * 4;
    if (base >= E) return;
    if (base + 3 < E) {
        int4 s = *(const int4*)(ei + base);
        int4 d = *(const int4*)(ei + E + base);
        int ss[4] = {s.x, s.y, s.z, s.w};
        int ds[4] = {d.x, d.y, d.z, d.w};
        float ws[4];
        #pragma unroll
        for (int j = 0; j < 4; j++) ws[j] = g_dinv[ss[j]] * g_dinv[ds[j]];
        #pragma unroll
        for (int j = 0; j < 4; j++) {
            int p = atomicAdd(&g_cursor[ds[j]], 1);
            g_cw[p] = make_int2(ss[j], __float_as_int(ws[j]));
        }
    } else {
        for (int j = base; j < E; j++) {
            int sj = ei[j], dj = ei[E + j];
            float w = g_dinv[sj] * g_dinv[dj];
            int p = atomicAdd(&g_cursor[dj], 1);
            g_cw[p] = make_int2(sj, __float_as_int(w));
        }
    }
}

// ---------------- GEMM: H[M x 128] = X @ W via 3x bf16 mma.m16n8k16 -------------
// blk0: row-block offset, enabling half-graph pipelined launches.
#define SXB 36    // X smem row stride (uint32 pairs): A bank = (4g+t)%32 bijective
#define SWB 136   // W smem row stride (uint32):       B bank = (8t+g)%32 bijective
#define GEMM_SMEM ((2 * 128 * SXB + 2 * 64 * SWB) * (int)sizeof(uint32_t))

__global__ __launch_bounds__(256, 1)
void k_gemm_mma(const float* __restrict__ X,
                const uint32_t* __restrict__ Wh, const uint32_t* __restrict__ Wl,
                __half2* __restrict__ H, int M, int blk0) {
    extern __shared__ uint32_t smu[];
    uint32_t* sXh = smu;
    uint32_t* sXl = sXh + 128 * SXB;
    uint32_t* sWh = sXl + 128 * SXB;        // full K: 64 pair-rows
    uint32_t* sWl = sWh + 64 * SWB;

    const int tid  = threadIdx.x;
    const int lane = tid & 31;
    const int g    = lane >> 2;
    const int t    = lane & 3;
    const int warp = tid >> 5;
    const int wm   = (warp >> 1) * 32;   // warp M offset
    const int wn   = (warp & 1) * 64;    // warp N offset
    const int row0 = (blockIdx.x + blk0) * 128;

    // ---- async copy of both W splits (full K, pre-packed; pure copy)
    {
        uint32_t swh = (uint32_t)__cvta_generic_to_shared(sWh);
        uint32_t swl = (uint32_t)__cvta_generic_to_shared(sWl);
        #pragma unroll
        for (int it = 0; it < 8; it++) {
            int e4 = tid + it * 256;        // 0..2047 (16B chunks)
            int r  = e4 >> 5;               // pair row 0..63
            int c4 = (e4 & 31) * 4;         // n col (x4 uint32)
            cp_async16(swh + (uint32_t)(r * SWB + c4) * 4, Wh + r * 128 + c4);
            cp_async16(swl + (uint32_t)(r * SWB + c4) * 4, Wl + r * 128 + c4);
        }
        asm volatile("cp.async.commit_group;");
    }

    float acc[2][8][4];
    #pragma unroll
    for (int a = 0; a < 2; a++)
        #pragma unroll
        for (int b = 0; b < 8; b++)
            #pragma unroll
            for (int c = 0; c < 4; c++) acc[a][b][c] = 0.f;

    #pragma unroll
    for (int kc = 0; kc < 2; kc++) {
        // load + split X chunk [128 rows][64 k = 32 pairs]
        #pragma unroll
        for (int it = 0; it < 8; it++) {
            int e4 = tid + it * 256;        // 0..2047
            int r  = e4 >> 4;               // row 0..127
            int c4 = e4 & 15;               // float4 index in row
            float4 v = make_float4(0.f, 0.f, 0.f, 0.f);
            if (row0 + r < M)
                v = *(const float4*)&X[(size_t)(row0 + r) * D + kc * 64 + c4 * 4];
            uint32_t hp0, lp0, hp1, lp1;
            bf16_split2(make_float2(v.x, v.y), hp0, lp0);
            bf16_split2(make_float2(v.z, v.w), hp1, lp1);
            *(uint2*)&sXh[r * SXB + c4 * 2] = make_uint2(hp0, hp1);
            *(uint2*)&sXl[r * SXB + c4 * 2] = make_uint2(lp0, lp1);
        }
        if (kc == 0) asm volatile("cp.async.wait_group 0;");
        __syncthreads();

        #pragma unroll
        for (int ks = 0; ks < 4; ks++) {       // 4 x K16 per 64-k chunk
            int kp  = ks * 8;                  // pair offset in chunk
            int kgp = kc * 32 + kp;            // global W pair row
            uint32_t ah[2][4], al[2][4];
            #pragma unroll
            for (int mi = 0; mi < 2; mi++) {
                int mb = wm + mi * 16;
                ah[mi][0] = sXh[(mb + g)     * SXB + kp + t];
                ah[mi][1] = sXh[(mb + g + 8) * SXB + kp + t];
                ah[mi][2] = sXh[(mb + g)     * SXB + kp + t + 4];
                ah[mi][3] = sXh[(mb + g + 8) * SXB + kp + t + 4];
                al[mi][0] = sXl[(mb + g)     * SXB + kp + t];
                al[mi][1] = sXl[(mb + g + 8) * SXB + kp + t];
                al[mi][2] = sXl[(mb + g)     * SXB + kp + t + 4];
                al[mi][3] = sXl[(mb + g + 8) * SXB + kp + t + 4];
            }
            #pragma unroll
            for (int j = 0; j < 8; j++) {
                int nb = wn + j * 8;
                uint32_t bh0 = sWh[(kgp + t)     * SWB + nb + g];
                uint32_t bh1 = sWh[(kgp + t + 4) * SWB + nb + g];
                uint32_t bl0 = sWl[(kgp + t)     * SWB + nb + g];
                uint32_t bl1 = sWl[(kgp + t + 4) * SWB + nb + g];
                #pragma unroll
                for (int mi = 0; mi < 2; mi++) {
                    mma_bf16(acc[mi][j], ah[mi], bh0, bh1);
                    mma_bf16(acc[mi][j], ah[mi], bl0, bl1);
                    mma_bf16(acc[mi][j], al[mi], bh0, bh1);
                }
            }
        }
        __syncthreads();
    }

    // epilogue: store fp16 pairs (64 half2 per row)
    #pragma unroll
    for (int mi = 0; mi < 2; mi++) {
        int r0 = row0 + wm + mi * 16 + g;
        #pragma unroll
        for (int j = 0; j < 8; j++) {
            int colp = (wn + j * 8 + 2 * t) >> 1;   // half2 index in row
            if (r0 < M)
                H[(size_t)r0 * 64 + colp] =
                    __floats2half2_rn(acc[mi][j][0], acc[mi][j][1]);
            if (r0 + 8 < M)
                H[(size_t)(r0 + 8) * 64 + colp] =
                    __floats2half2_rn(acc[mi][j][2], acc[mi][j][3]);
        }
    }
}

// ---------------- aggregation over node range [n0, n1) --------------------------
__global__ void k_agg(const float* __restrict__ bias, float* __restrict__ Y,
                      int n0, int n1, int do_relu) {
    int gt   = blockIdx.x * blockDim.x + threadIdx.x;
    int node = n0 + (gt >> 5);
    int lane = gt & 31;
    if (node >= n1) return;

    const uint2* H2 = (const uint2*)g_H;
    float di = g_dinv[node];
    float sw = di * di;
    float4 hs = h4_to_f4(H2[(size_t)node * 32 + lane]);
    float4 acc = make_float4(hs.x * sw, hs.y * sw, hs.z * sw, hs.w * sw);

    int i   = g_rowstart[node];
    int end = g_rowstart[node + 1];
    for (; i + 3 < end; i += 4) {
        int2  e0 = g_cw[i],     e1 = g_cw[i + 1];
        int2  e2 = g_cw[i + 2], e3 = g_cw[i + 3];
        float w0 = __int_as_float(e0.y), w1 = __int_as_float(e1.y);
        float w2 = __int_as_float(e2.y), w3 = __int_as_float(e3.y);
        float4 h0 = h4_to_f4(H2[(size_t)e0.x * 32 + lane]);
        float4 h1 = h4_to_f4(H2[(size_t)e1.x * 32 + lane]);
        float4 h2 = h4_to_f4(H2[(size_t)e2.x * 32 + lane]);
        float4 h3 = h4_to_f4(H2[(size_t)e3.x * 32 + lane]);
        acc.x += w0 * h0.x + w1 * h1.x + w2 * h2.x + w3 * h3.x;
        acc.y += w0 * h0.y + w1 * h1.y + w2 * h2.y + w3 * h3.y;
        acc.z += w0 * h0.z + w1 * h1.z + w2 * h2.z + w3 * h3.z;
        acc.w += w0 * h0.w + w1 * h1.w + w2 * h2.w + w3 * h3.w;
    }
    for (; i < end; i++) {
        int2  e = g_cw[i];
        float w = __int_as_float(e.y);
        float4 h = h4_to_f4(H2[(size_t)e.x * 32 + lane]);
        acc.x += w * h.x; acc.y += w * h.y; acc.z += w * h.z; acc.w += w * h.w;
    }

    float4 b4 = ((const float4*)bias)[lane];
    acc.x += b4.x; acc.y += b4.y; acc.z += b4.z; acc.w += b4.w;
    if (do_relu) {
        acc.x = fmaxf(acc.x, 0.f); acc.y = fmaxf(acc.y, 0.f);
        acc.z = fmaxf(acc.z, 0.f); acc.w = fmaxf(acc.w, 0.f);
    }
    ((float4*)Y)[(size_t)node * 32 + lane] = acc;
}

// ---------------- decoder: out[e] = dot(X[u], X[v]) ----------------
__global__ void k_decode(const float* __restrict__ X, const int* __restrict__ eli,
                         float* __restrict__ out, int EL) {
    int gt   = blockIdx.x * blockDim.x + threadIdx.x;
    int e    = gt >> 5;
    int lane = gt & 31;
    if (e >= EL) return;
    int u = eli[e];
    int v = eli[EL + e];
    const float4* X4 = (const float4*)X;
    float4 a = X4[(size_t)u * 32 + lane];
    float4 b = X4[(size_t)v * 32 + lane];
    float s = a.x * b.x + a.y * b.y + a.z * b.z + a.w * b.w;
    #pragma unroll
    for (int o = 16; o > 0; o >>= 1) s += __shfl_xor_sync(0xffffffffu, s, o);
    if (lane == 0) out[e] = s;
}

// ---------------- launch ----------------
extern "C" void kernel_launch(void* const* d_in, const int* in_sizes, int n_in,
                              void* d_out, int out_size) {
    const float* x   = (const float*)d_in[0];
    const float* W1  = (const float*)d_in[1];
    const float* b1  = (const float*)d_in[2];
    const float* W2  = (const float*)d_in[3];
    const float* b2  = (const float*)d_in[4];
    const float* W3  = (const float*)d_in[5];
    const float* b3  = (const float*)d_in[6];
    const int*   ei  = (const int*)d_in[7];
    const int*   eli = (const int*)d_in[8];
    float*       out = (float*)d_out;

    int N  = in_sizes[0] / D;
    int E  = in_sizes[7] / 2;
    int EL = in_sizes[8] / 2;

    float *pA, *pB;
    __half2* pH;
    uint32_t *pWh, *pWl;
    cudaGetSymbolAddress((void**)&pH,  g_H);
    cudaGetSymbolAddress((void**)&pA,  g_A);
    cudaGetSymbolAddress((void**)&pB,  g_B);
    cudaGetSymbolAddress((void**)&pWh, g_Wh);
    cudaGetSymbolAddress((void**)&pWl, g_Wl);

    cudaFuncSetAttribute(k_gemm_mma, cudaFuncAttributeMaxDynamicSharedMemorySize,
                         GEMM_SMEM);

    int nb     = (N + 1023) / 1024;
    int gb     = (N + 127) / 128;        // total gemm blocks
    int gbA    = gb / 2;                 // half A blocks
    int gbB    = gb - gbA;
    int NA     = gbA * 128;              // nodes in half A (aligned to gemm tile)
    int aggA   = (NA * 32 + 255) / 256;
    int aggB   = (int)(((size_t)(N - NA) * 32 + 255) / 256);
    int aggAll = (int)(((size_t)N * 32 + 255) / 256);

    // ---- fork: CSR build on s2, concurrent with W-split + GEMM-1 on stream 0 ----
    cudaEventRecord(evFork, 0);
    cudaStreamWaitEvent(s2, evFork, 0);
    k_count  <<<(E / 4 + 255) / 256, 256, 0, s2>>>(ei + E, E);
    k_scan_lb<<<nb, 1024, 0, s2>>>(N);
    k_fill   <<<(E / 4 + 255) / 256, 256, 0, s2>>>(ei, E);
    cudaEventRecord(evJoin, s2);

    // ---- W pre-split (all layers) then layer-1 GEMM (full), overlapping CSR ----
    k_wsplit<<<dim3(32, 3), 256>>>(W1, W2, W3);
    k_gemm_mma<<<gb, 256, GEMM_SMEM>>>(x, pWh, pWl, pH, N, 0);

    // ---- join: H1 + CSR both ready ----
    cudaStreamWaitEvent(0, evJoin, 0);
    cudaEventRecord(evR1, 0);

    // ============ pipelined layers: agg_i(B) overlaps gemm_{i+1}(A) ============
    // layer 1 agg
    k_agg<<<aggA, 256>>>(b1, pA, 0, NA, 1);                 // main: agg1(A)
    cudaStreamWaitEvent(s2, evR1, 0);
    k_agg<<<aggB, 256, 0, s2>>>(b1, pA, NA, N, 1);          // s2:   agg1(B)
    cudaEventRecord(eB1, s2);

    // layer 2 gemm (A needs only agg1(A); B waits for agg1(B))
    k_gemm_mma<<<gbA, 256, GEMM_SMEM>>>(pA, pWh + 8192, pWl + 8192, pH, N, 0);
    cudaStreamWaitEvent(0, eB1, 0);
    k_gemm_mma<<<gbB, 256, GEMM_SMEM>>>(pA, pWh + 8192, pWl + 8192, pH, N, gbA);
    cudaEventRecord(eG2, 0);

    // layer 2 agg
    k_agg<<<aggA, 256>>>(b2, pB, 0, NA, 1);                 // main: agg2(A)
    cudaStreamWaitEvent(s2, eG2, 0);
    k_agg<<<aggB, 256, 0, s2>>>(b2, pB, NA, N, 1);          // s2:   agg2(B)
    cudaEventRecord(eB2, s2);

    // layer 3 gemm
    k_gemm_mma<<<gbA, 256, GEMM_SMEM>>>(pB, pWh + 16384, pWl + 16384, pH, N, 0);
    cudaStreamWaitEvent(0, eB2, 0);
    k_gemm_mma<<<gbB, 256, GEMM_SMEM>>>(pB, pWh + 16384, pWl + 16384, pH, N, gbA);
    cudaEventRecord(eG3, 0);

    // layer 3 agg (no relu)
    k_agg<<<aggA, 256>>>(b3, pA, 0, NA, 0);                 // main: agg3(A)
    cudaStreamWaitEvent(s2, eG3, 0);
    k_agg<<<aggB, 256, 0, s2>>>(b3, pA, NA, N, 0);          // s2:   agg3(B)
    cudaEventRecord(eB3, s2);

    // ---- decoder (needs full agg3) ----
    cudaStreamWaitEvent(0, eB3, 0);
    k_decode<<<(int)(((size_t)EL * 32 + 255) / 256), 256>>>(pA, eli, out, EL);
}